// round 1
// baseline (speedup 1.0000x reference)
#include <cuda_runtime.h>
#include <cstdint>

// Problem constants
#define BB   4
#define TT   2048
#define DIM  1024
#define NH   16
#define HD   64
#define MROWS (BB*TT)          // 8192

// ---------------------------------------------------------------------------
// Scratch (device globals; no runtime allocation allowed)
// ---------------------------------------------------------------------------
__device__ float g_qkv[(size_t)MROWS * 3 * DIM];   // [8192, 3072]
__device__ float g_q[(size_t)MROWS * DIM];         // [b,h,t,d]
__device__ float g_k[(size_t)MROWS * DIM];
__device__ float g_v[(size_t)MROWS * DIM];
__device__ float g_o[(size_t)MROWS * DIM];         // [b,t,h,d] == [8192,1024]

// ---------------------------------------------------------------------------
// Tiled fp32 GEMM: C[M,N] = A[M,K] @ B[K,N].  BM=BN=128, BK=16, 256 thr, 8x8.
// M,N,K all divisible by tile sizes here (8192 x {3072,1024} x 1024).
// ---------------------------------------------------------------------------
__device__ __forceinline__ void gemm_body(const float* __restrict__ A,
                                          const float* __restrict__ Bw,
                                          float* __restrict__ C,
                                          int N, int K) {
    __shared__ __align__(16) float As[16][128];
    __shared__ __align__(16) float Bs[16][128];

    const int bm  = blockIdx.y * 128;
    const int bn  = blockIdx.x * 128;
    const int tid = threadIdx.x;
    const int tx  = tid & 15;
    const int ty  = tid >> 4;

    float acc[8][8];
#pragma unroll
    for (int i = 0; i < 8; i++)
#pragma unroll
        for (int j = 0; j < 8; j++) acc[i][j] = 0.f;

    for (int k0 = 0; k0 < K; k0 += 16) {
        // Load A tile (128x16) transposed into As[k][m]; 512 float4, 2/thread
#pragma unroll
        for (int i = 0; i < 2; i++) {
            int f   = tid * 2 + i;
            int row = f >> 2;
            int c4  = (f & 3) << 2;
            float4 v = *(const float4*)(A + (size_t)(bm + row) * K + k0 + c4);
            As[c4 + 0][row] = v.x;
            As[c4 + 1][row] = v.y;
            As[c4 + 2][row] = v.z;
            As[c4 + 3][row] = v.w;
            // Load B tile (16x128) directly
            int rowb = f >> 5;
            int cb   = (f & 31) << 2;
            *(float4*)&Bs[rowb][cb] =
                *(const float4*)(Bw + (size_t)(k0 + rowb) * N + bn + cb);
        }
        __syncthreads();

#pragma unroll
        for (int k = 0; k < 16; k++) {
            float4 a0 = *(const float4*)&As[k][ty * 8];
            float4 a1 = *(const float4*)&As[k][ty * 8 + 4];
            float4 b0 = *(const float4*)&Bs[k][tx * 8];
            float4 b1 = *(const float4*)&Bs[k][tx * 8 + 4];
            float a[8] = {a0.x, a0.y, a0.z, a0.w, a1.x, a1.y, a1.z, a1.w};
            float b[8] = {b0.x, b0.y, b0.z, b0.w, b1.x, b1.y, b1.z, b1.w};
#pragma unroll
            for (int i = 0; i < 8; i++)
#pragma unroll
                for (int j = 0; j < 8; j++) acc[i][j] += a[i] * b[j];
        }
        __syncthreads();
    }

#pragma unroll
    for (int i = 0; i < 8; i++) {
        float4 c0 = make_float4(acc[i][0], acc[i][1], acc[i][2], acc[i][3]);
        float4 c1 = make_float4(acc[i][4], acc[i][5], acc[i][6], acc[i][7]);
        float* dst = C + (size_t)(bm + ty * 8 + i) * N + bn + tx * 8;
        *(float4*)dst       = c0;
        *(float4*)(dst + 4) = c1;
    }
}

__global__ __launch_bounds__(256) void gemm_qkv_kernel(const float* __restrict__ x,
                                                       const float* __restrict__ W) {
    gemm_body(x, W, g_qkv, 3 * DIM, DIM);
}

__global__ __launch_bounds__(256) void gemm_proj_kernel(const float* __restrict__ W,
                                                        float* __restrict__ out) {
    gemm_body(g_o, W, out, DIM, DIM);
}

// ---------------------------------------------------------------------------
// RoPE + split/transpose: g_qkv [row=b*T+t, 3*DIM] -> g_q/g_k/g_v [b,h,t,d]
// thread handles one (row, h, pair i): q pair, k pair, v pair.
// ---------------------------------------------------------------------------
__global__ __launch_bounds__(256) void rope_split_kernel(const float* __restrict__ fcos,
                                                         const float* __restrict__ fsin) {
    int idx = blockIdx.x * 256 + threadIdx.x;   // < 8192 * 512
    int row = idx >> 9;                          // b*T + t
    int rem = idx & 511;
    int h   = rem >> 5;
    int i   = rem & 31;
    int t   = row & (TT - 1);
    int b   = row >> 11;

    float c = fcos[t * (HD / 2) + i];
    float s = fsin[t * (HD / 2) + i];

    const float* base = g_qkv + (size_t)row * (3 * DIM) + h * HD + 2 * i;
    float2 q = *(const float2*)(base);
    float2 k = *(const float2*)(base + DIM);
    float2 v = *(const float2*)(base + 2 * DIM);

    size_t dst = ((size_t)(b * NH + h) * TT + t) * HD + 2 * i;
    float2 qo = make_float2(q.x * c - q.y * s, q.x * s + q.y * c);
    float2 ko = make_float2(k.x * c - k.y * s, k.x * s + k.y * c);
    *(float2*)(g_q + dst) = qo;
    *(float2*)(g_k + dst) = ko;
    *(float2*)(g_v + dst) = v;
}

// ---------------------------------------------------------------------------
// Flash attention (fp32, no mask — mask is all ones by construction).
// blockIdx.y = b*H + h, blockIdx.x = q-row tile (128 rows, 1 row/thread).
// K/V tiles of 64 keys staged in smem; online softmax over chunks of 16.
// ---------------------------------------------------------------------------
__global__ __launch_bounds__(128, 2) void attn_kernel() {
    const int bh = blockIdx.y;                       // 0..63
    const int r  = blockIdx.x * 128 + threadIdx.x;   // query row in [0,T)

    __shared__ __align__(16) float Ks[64][HD];
    __shared__ __align__(16) float Vs[64][HD];

    const size_t qoff = ((size_t)bh * TT + r) * HD;
    float4 q4[16];
#pragma unroll
    for (int j = 0; j < 16; j++) q4[j] = *(const float4*)(g_q + qoff + j * 4);

    float4 o4[16];
#pragma unroll
    for (int j = 0; j < 16; j++) o4[j] = make_float4(0.f, 0.f, 0.f, 0.f);

    float m = -3.0e38f;
    float l = 0.f;

    for (int kt = 0; kt < TT; kt += 64) {
        const float4* Kg = (const float4*)(g_k + ((size_t)bh * TT + kt) * HD);
        const float4* Vg = (const float4*)(g_v + ((size_t)bh * TT + kt) * HD);
#pragma unroll
        for (int i = 0; i < 8; i++) {
            int f = threadIdx.x + i * 128;           // 1024 float4 per tile
            ((float4*)Ks)[f] = Kg[f];
            ((float4*)Vs)[f] = Vg[f];
        }
        __syncthreads();

        for (int c0 = 0; c0 < 64; c0 += 16) {
            float s[16];
#pragma unroll
            for (int kk = 0; kk < 16; kk++) {
                const float4* kr = (const float4*)&Ks[c0 + kk][0];
                float acc0 = 0.f, acc1 = 0.f;
#pragma unroll
                for (int j = 0; j < 16; j++) {
                    float4 kv = kr[j];
                    acc0 += q4[j].x * kv.x;
                    acc1 += q4[j].y * kv.y;
                    acc0 += q4[j].z * kv.z;
                    acc1 += q4[j].w * kv.w;
                }
                s[kk] = (acc0 + acc1) * 0.125f;      // HD^-0.5
            }
            float mn = m;
#pragma unroll
            for (int kk = 0; kk < 16; kk++) mn = fmaxf(mn, s[kk]);
            float corr = __expf(m - mn);
            m = mn;
            l *= corr;
#pragma unroll
            for (int j = 0; j < 16; j++) {
                o4[j].x *= corr; o4[j].y *= corr; o4[j].z *= corr; o4[j].w *= corr;
            }
#pragma unroll
            for (int kk = 0; kk < 16; kk++) {
                float p = __expf(s[kk] - m);
                l += p;
                const float4* vr = (const float4*)&Vs[c0 + kk][0];
#pragma unroll
                for (int j = 0; j < 16; j++) {
                    float4 vv = vr[j];
                    o4[j].x += p * vv.x;
                    o4[j].y += p * vv.y;
                    o4[j].z += p * vv.z;
                    o4[j].w += p * vv.w;
                }
            }
        }
        __syncthreads();
    }

    float inv = 1.f / l;
    int b = bh >> 4;
    int h = bh & 15;
    float* Og = g_o + ((size_t)(b * TT + r)) * DIM + h * HD;
#pragma unroll
    for (int j = 0; j < 16; j++) {
        float4 t = o4[j];
        t.x *= inv; t.y *= inv; t.z *= inv; t.w *= inv;
        *(float4*)(Og + j * 4) = t;
    }
}

// ---------------------------------------------------------------------------
// Launch
// ---------------------------------------------------------------------------
extern "C" void kernel_launch(void* const* d_in, const int* in_sizes, int n_in,
                              void* d_out, int out_size) {
    (void)in_sizes; (void)n_in; (void)out_size;
    const float* x     = (const float*)d_in[0];   // [4,2048,1024]
    const float* fcos  = (const float*)d_in[1];   // [2048,32]
    const float* fsin  = (const float*)d_in[2];   // [2048,32]
    // d_in[3] = mask (all true) — unused
    const float* Wqkv  = (const float*)d_in[4];   // [1024,3072]
    const float* Wproj = (const float*)d_in[5];   // [1024,1024]
    float* out = (float*)d_out;                   // [4,2048,1024]

    // 1) QKV GEMM: [8192,1024] @ [1024,3072]
    {
        dim3 grid(3 * DIM / 128, MROWS / 128);
        gemm_qkv_kernel<<<grid, 256>>>(x, Wqkv);
    }
    // 2) RoPE + split to [b,h,t,d]
    {
        int total = MROWS * (NH * HD / 2);        // 8192*512
        rope_split_kernel<<<total / 256, 256>>>(fcos, fsin);
    }
    // 3) Flash attention
    {
        dim3 grid(TT / 128, BB * NH);
        attn_kernel<<<grid, 128>>>();
    }
    // 4) Output projection: [8192,1024] @ [1024,1024]
    {
        dim3 grid(DIM / 128, MROWS / 128);
        gemm_proj_kernel<<<grid, 256>>>(Wproj, out);
    }
}

// round 3
// speedup vs baseline: 3.0821x; 3.0821x over previous
#include <cuda_runtime.h>
#include <cstdint>

#define BB   4
#define TT   2048
#define DIM  1024
#define NH   16
#define HD   64
#define MROWS (BB*TT)          // 8192

// ---------------------------------------------------------------------------
// Scratch
// ---------------------------------------------------------------------------
__device__ float g_qkv[(size_t)MROWS * 3 * DIM];
__device__ float g_q[(size_t)MROWS * DIM];         // [b,h,t,d]
__device__ float g_k[(size_t)MROWS * DIM];
__device__ float g_v[(size_t)MROWS * DIM];
__device__ float g_o[(size_t)MROWS * DIM];         // [b,t,h*d]

// ---------------------------------------------------------------------------
// tf32 helpers
// ---------------------------------------------------------------------------
__device__ __forceinline__ uint32_t f2tf32(float x) {
    uint32_t r;
    asm("cvt.rna.tf32.f32 %0, %1;" : "=r"(r) : "f"(x));
    return r;
}

__device__ __forceinline__ void mma_tf32(float c[4], const uint32_t a[4],
                                         const uint32_t b[2]) {
    asm volatile(
        "mma.sync.aligned.m16n8k8.row.col.f32.tf32.tf32.f32 "
        "{%0,%1,%2,%3}, {%4,%5,%6,%7}, {%8,%9}, {%0,%1,%2,%3};\n"
        : "+f"(c[0]), "+f"(c[1]), "+f"(c[2]), "+f"(c[3])
        : "r"(a[0]), "r"(a[1]), "r"(a[2]), "r"(a[3]), "r"(b[0]), "r"(b[1]));
}

// ---------------------------------------------------------------------------
// tf32 GEMM: C[M,N] = A[M,K] @ B[K,N].  BM=BN=128, BK=16, 256 thr, 8 warps.
// Warp grid 2(m) x 4(n): warp tile 64x32.  Smem stride 136 (8 mod 32) ->
// conflict-free fragment LDS.
// ---------------------------------------------------------------------------
#define GS 136
__device__ __forceinline__ void gemm_tf32_body(const float* __restrict__ A,
                                               const float* __restrict__ Bw,
                                               float* __restrict__ C,
                                               int N, int K) {
    __shared__ __align__(16) float As[16][GS];
    __shared__ __align__(16) float Bs[16][GS];

    const int bm   = blockIdx.y * 128;
    const int bn   = blockIdx.x * 128;
    const int tid  = threadIdx.x;
    const int wid  = tid >> 5;
    const int lane = tid & 31;
    const int g    = lane >> 2;      // groupID
    const int t    = lane & 3;       // threadID_in_group
    const int wm   = (wid >> 2) * 64;
    const int wn   = (wid & 3) * 32;

    float acc[4][4][4];
#pragma unroll
    for (int mt = 0; mt < 4; mt++)
#pragma unroll
        for (int nt = 0; nt < 4; nt++)
#pragma unroll
            for (int r = 0; r < 4; r++) acc[mt][nt][r] = 0.f;

    for (int k0 = 0; k0 < K; k0 += 16) {
#pragma unroll
        for (int i = 0; i < 2; i++) {
            int f = tid * 2 + i;
            // A tile 128x16 -> As[k][m] (transposed)
            int row = f >> 2, c4 = (f & 3) << 2;
            float4 va = *(const float4*)(A + (size_t)(bm + row) * K + k0 + c4);
            As[c4 + 0][row] = __uint_as_float(f2tf32(va.x));
            As[c4 + 1][row] = __uint_as_float(f2tf32(va.y));
            As[c4 + 2][row] = __uint_as_float(f2tf32(va.z));
            As[c4 + 3][row] = __uint_as_float(f2tf32(va.w));
            // B tile 16x128 -> Bs[k][n]
            int rowb = f >> 5, cb = (f & 31) << 2;
            float4 vb = *(const float4*)(Bw + (size_t)(k0 + rowb) * N + bn + cb);
            Bs[rowb][cb + 0] = __uint_as_float(f2tf32(vb.x));
            Bs[rowb][cb + 1] = __uint_as_float(f2tf32(vb.y));
            Bs[rowb][cb + 2] = __uint_as_float(f2tf32(vb.z));
            Bs[rowb][cb + 3] = __uint_as_float(f2tf32(vb.w));
        }
        __syncthreads();

#pragma unroll
        for (int ks = 0; ks < 16; ks += 8) {
            uint32_t a[4][4];
#pragma unroll
            for (int mt = 0; mt < 4; mt++) {
                int m = wm + mt * 16;
                a[mt][0] = __float_as_uint(As[ks + t][m + g]);
                a[mt][1] = __float_as_uint(As[ks + t][m + g + 8]);
                a[mt][2] = __float_as_uint(As[ks + t + 4][m + g]);
                a[mt][3] = __float_as_uint(As[ks + t + 4][m + g + 8]);
            }
            uint32_t b[4][2];
#pragma unroll
            for (int nt = 0; nt < 4; nt++) {
                int n = wn + nt * 8;
                b[nt][0] = __float_as_uint(Bs[ks + t][n + g]);
                b[nt][1] = __float_as_uint(Bs[ks + t + 4][n + g]);
            }
#pragma unroll
            for (int mt = 0; mt < 4; mt++)
#pragma unroll
                for (int nt = 0; nt < 4; nt++)
                    mma_tf32(acc[mt][nt], a[mt], b[nt]);
        }
        __syncthreads();
    }

#pragma unroll
    for (int mt = 0; mt < 4; mt++) {
#pragma unroll
        for (int nt = 0; nt < 4; nt++) {
            int r0 = bm + wm + mt * 16 + g;
            int cc = bn + wn + nt * 8 + 2 * t;
            *(float2*)(C + (size_t)r0 * N + cc)       = make_float2(acc[mt][nt][0], acc[mt][nt][1]);
            *(float2*)(C + (size_t)(r0 + 8) * N + cc) = make_float2(acc[mt][nt][2], acc[mt][nt][3]);
        }
    }
}

__global__ __launch_bounds__(256) void gemm_qkv_kernel(const float* __restrict__ x,
                                                       const float* __restrict__ W) {
    gemm_tf32_body(x, W, g_qkv, 3 * DIM, DIM);
}
__global__ __launch_bounds__(256) void gemm_proj_kernel(const float* __restrict__ W,
                                                        float* __restrict__ out) {
    gemm_tf32_body(g_o, W, out, DIM, DIM);
}

// ---------------------------------------------------------------------------
// RoPE + split/transpose
// ---------------------------------------------------------------------------
__global__ __launch_bounds__(256) void rope_split_kernel(const float* __restrict__ fcos,
                                                         const float* __restrict__ fsin) {
    int idx = blockIdx.x * 256 + threadIdx.x;
    int row = idx >> 9;
    int rem = idx & 511;
    int h   = rem >> 5;
    int i   = rem & 31;
    int t   = row & (TT - 1);
    int b   = row >> 11;

    float c = fcos[t * (HD / 2) + i];
    float s = fsin[t * (HD / 2) + i];

    const float* base = g_qkv + (size_t)row * (3 * DIM) + h * HD + 2 * i;
    float2 q = *(const float2*)(base);
    float2 k = *(const float2*)(base + DIM);
    float2 v = *(const float2*)(base + 2 * DIM);

    size_t dst = ((size_t)(b * NH + h) * TT + t) * HD + 2 * i;
    *(float2*)(g_q + dst) = make_float2(q.x * c - q.y * s, q.x * s + q.y * c);
    *(float2*)(g_k + dst) = make_float2(k.x * c - k.y * s, k.x * s + k.y * c);
    *(float2*)(g_v + dst) = v;
}

// ---------------------------------------------------------------------------
// Flash attention with tf32 mma.  Block: 256 thr (8 warps), 128 q rows
// (16/warp).  KV tile = 64.  Softmax scale folded into Q fragments.
// Ks stride 68 (4 mod 32), Vs stride 72 (8 mod 32): conflict-free B-frag LDS.
// ---------------------------------------------------------------------------
#define KS_S 68
#define VS_S 72
__global__ __launch_bounds__(256, 1) void attn_kernel() {
    __shared__ __align__(16) float Ks[64][KS_S];
    __shared__ __align__(16) float Vs[64][VS_S];

    const int bh   = blockIdx.y;
    const int q0   = blockIdx.x * 128;
    const int tid  = threadIdx.x;
    const int wid  = tid >> 5;
    const int lane = tid & 31;
    const int g    = lane >> 2;
    const int t    = lane & 3;

    // Q fragments (scaled by HD^-0.5), rows q0 + wid*16 + {g, g+8}
    const size_t qbase = ((size_t)bh * TT + q0 + wid * 16) * HD;
    uint32_t qa[8][4];
#pragma unroll
    for (int kt = 0; kt < 8; kt++) {
        qa[kt][0] = f2tf32(g_q[qbase + (size_t)g * HD + kt * 8 + t] * 0.125f);
        qa[kt][1] = f2tf32(g_q[qbase + (size_t)(g + 8) * HD + kt * 8 + t] * 0.125f);
        qa[kt][2] = f2tf32(g_q[qbase + (size_t)g * HD + kt * 8 + t + 4] * 0.125f);
        qa[kt][3] = f2tf32(g_q[qbase + (size_t)(g + 8) * HD + kt * 8 + t + 4] * 0.125f);
    }

    float O[8][4];
#pragma unroll
    for (int nt = 0; nt < 8; nt++)
#pragma unroll
        for (int r = 0; r < 4; r++) O[nt][r] = 0.f;
    float m0 = -1e30f, m1 = -1e30f, l0 = 0.f, l1 = 0.f;

    for (int kv0 = 0; kv0 < TT; kv0 += 64) {
        const float* Kg = g_k + ((size_t)bh * TT + kv0) * HD;
        const float* Vg = g_v + ((size_t)bh * TT + kv0) * HD;
#pragma unroll
        for (int i = 0; i < 4; i++) {
            int idx = tid + i * 256;               // 1024 float4 per matrix
            int row = idx >> 4, c4 = (idx & 15) << 2;
            float4 kv = *(const float4*)(Kg + (size_t)row * HD + c4);
            Ks[row][c4 + 0] = __uint_as_float(f2tf32(kv.x));
            Ks[row][c4 + 1] = __uint_as_float(f2tf32(kv.y));
            Ks[row][c4 + 2] = __uint_as_float(f2tf32(kv.z));
            Ks[row][c4 + 3] = __uint_as_float(f2tf32(kv.w));
            float4 vv = *(const float4*)(Vg + (size_t)row * HD + c4);
            Vs[row][c4 + 0] = __uint_as_float(f2tf32(vv.x));
            Vs[row][c4 + 1] = __uint_as_float(f2tf32(vv.y));
            Vs[row][c4 + 2] = __uint_as_float(f2tf32(vv.z));
            Vs[row][c4 + 3] = __uint_as_float(f2tf32(vv.w));
        }
        __syncthreads();

        // S = Q @ K^T : warp computes [16 x 64]
        float s[8][4];
#pragma unroll
        for (int nt = 0; nt < 8; nt++)
#pragma unroll
            for (int r = 0; r < 4; r++) s[nt][r] = 0.f;
#pragma unroll
        for (int kt = 0; kt < 8; kt++) {
            uint32_t kb[8][2];
#pragma unroll
            for (int nt = 0; nt < 8; nt++) {
                kb[nt][0] = __float_as_uint(Ks[nt * 8 + g][kt * 8 + t]);
                kb[nt][1] = __float_as_uint(Ks[nt * 8 + g][kt * 8 + t + 4]);
            }
#pragma unroll
            for (int nt = 0; nt < 8; nt++)
                mma_tf32(s[nt], qa[kt], kb[nt]);
        }

        // online softmax
        float mx0 = -1e30f, mx1 = -1e30f;
#pragma unroll
        for (int nt = 0; nt < 8; nt++) {
            mx0 = fmaxf(mx0, fmaxf(s[nt][0], s[nt][1]));
            mx1 = fmaxf(mx1, fmaxf(s[nt][2], s[nt][3]));
        }
        mx0 = fmaxf(mx0, __shfl_xor_sync(0xffffffffu, mx0, 1));
        mx0 = fmaxf(mx0, __shfl_xor_sync(0xffffffffu, mx0, 2));
        mx1 = fmaxf(mx1, __shfl_xor_sync(0xffffffffu, mx1, 1));
        mx1 = fmaxf(mx1, __shfl_xor_sync(0xffffffffu, mx1, 2));
        float nm0 = fmaxf(m0, mx0), nm1 = fmaxf(m1, mx1);
        float c0 = __expf(m0 - nm0), c1 = __expf(m1 - nm1);
        m0 = nm0; m1 = nm1;
        l0 *= c0;  l1 *= c1;
#pragma unroll
        for (int nt = 0; nt < 8; nt++) {
            O[nt][0] *= c0; O[nt][1] *= c0;
            O[nt][2] *= c1; O[nt][3] *= c1;
        }
        uint32_t p[8][4];
#pragma unroll
        for (int nt = 0; nt < 8; nt++) {
            float e0 = __expf(s[nt][0] - m0);
            float e1 = __expf(s[nt][1] - m0);
            float e2 = __expf(s[nt][2] - m1);
            float e3 = __expf(s[nt][3] - m1);
            l0 += e0 + e1;  l1 += e2 + e3;
            p[nt][0] = f2tf32(e0); p[nt][1] = f2tf32(e1);
            p[nt][2] = f2tf32(e2); p[nt][3] = f2tf32(e3);
        }

        // O += P @ V.  Convert P from C-layout to A-layout via shuffles.
#pragma unroll
        for (int kt = 0; kt < 8; kt++) {
            int base = lane & 28;
            int src0 = base + (t >> 1);
            int src1 = base + (t >> 1) + 2;
            uint32_t x00 = __shfl_sync(0xffffffffu, p[kt][0], src0);
            uint32_t x01 = __shfl_sync(0xffffffffu, p[kt][1], src0);
            uint32_t x02 = __shfl_sync(0xffffffffu, p[kt][2], src0);
            uint32_t x03 = __shfl_sync(0xffffffffu, p[kt][3], src0);
            uint32_t x10 = __shfl_sync(0xffffffffu, p[kt][0], src1);
            uint32_t x11 = __shfl_sync(0xffffffffu, p[kt][1], src1);
            uint32_t x12 = __shfl_sync(0xffffffffu, p[kt][2], src1);
            uint32_t x13 = __shfl_sync(0xffffffffu, p[kt][3], src1);
            uint32_t pa[4];
            pa[0] = (t & 1) ? x01 : x00;
            pa[1] = (t & 1) ? x03 : x02;
            pa[2] = (t & 1) ? x11 : x10;
            pa[3] = (t & 1) ? x13 : x12;
#pragma unroll
            for (int nt = 0; nt < 8; nt++) {
                uint32_t vb[2];
                vb[0] = __float_as_uint(Vs[kt * 8 + t][nt * 8 + g]);
                vb[1] = __float_as_uint(Vs[kt * 8 + t + 4][nt * 8 + g]);
                mma_tf32(O[nt], pa, vb);
            }
        }
        __syncthreads();
    }

    // final normalize + write to g_o [b, t, h*d]
    l0 += __shfl_xor_sync(0xffffffffu, l0, 1);
    l0 += __shfl_xor_sync(0xffffffffu, l0, 2);
    l1 += __shfl_xor_sync(0xffffffffu, l1, 1);
    l1 += __shfl_xor_sync(0xffffffffu, l1, 2);
    float inv0 = 1.f / l0, inv1 = 1.f / l1;

    int b = bh >> 4, h = bh & 15;
    int r0 = q0 + wid * 16 + g;
#pragma unroll
    for (int nt = 0; nt < 8; nt++) {
        int cc = h * HD + nt * 8 + 2 * t;
        *(float2*)(g_o + ((size_t)(b * TT + r0)) * DIM + cc) =
            make_float2(O[nt][0] * inv0, O[nt][1] * inv0);
        *(float2*)(g_o + ((size_t)(b * TT + r0 + 8)) * DIM + cc) =
            make_float2(O[nt][2] * inv1, O[nt][3] * inv1);
    }
}

// ---------------------------------------------------------------------------
// Launch
// ---------------------------------------------------------------------------
extern "C" void kernel_launch(void* const* d_in, const int* in_sizes, int n_in,
                              void* d_out, int out_size) {
    (void)in_sizes; (void)n_in; (void)out_size;
    const float* x     = (const float*)d_in[0];
    const float* fcos  = (const float*)d_in[1];
    const float* fsin  = (const float*)d_in[2];
    const float* Wqkv  = (const float*)d_in[4];
    const float* Wproj = (const float*)d_in[5];
    float* out = (float*)d_out;

    {
        dim3 grid(3 * DIM / 128, MROWS / 128);
        gemm_qkv_kernel<<<grid, 256>>>(x, Wqkv);
    }
    {
        int total = MROWS * (NH * HD / 2);
        rope_split_kernel<<<total / 256, 256>>>(fcos, fsin);
    }
    {
        dim3 grid(TT / 128, BB * NH);
        attn_kernel<<<grid, 256>>>();
    }
    {
        dim3 grid(DIM / 128, MROWS / 128);
        gemm_proj_kernel<<<grid, 256>>>(Wproj, out);
    }
}

// round 6
// speedup vs baseline: 3.2136x; 1.0427x over previous
#include <cuda_runtime.h>
#include <cstdint>

#define BB   4
#define TT   2048
#define DIM  1024
#define NH   16
#define HD   64
#define MROWS (BB*TT)          // 8192

// ---------------------------------------------------------------------------
// Scratch
// ---------------------------------------------------------------------------
__device__ float g_qkv[(size_t)MROWS * 3 * DIM];
__device__ float g_q[(size_t)MROWS * DIM];         // [b,h,t,d]
__device__ float g_k[(size_t)MROWS * DIM];
__device__ float g_v[(size_t)MROWS * DIM];
__device__ float g_o[(size_t)MROWS * DIM];         // [b,t,h*d]

// ---------------------------------------------------------------------------
// helpers
// ---------------------------------------------------------------------------
__device__ __forceinline__ uint32_t f2tf32(float x) {
    uint32_t r;
    asm("cvt.rna.tf32.f32 %0, %1;" : "=r"(r) : "f"(x));
    return r;
}

__device__ __forceinline__ void mma_tf32(float c[4], const uint32_t a[4],
                                         const uint32_t b[2]) {
    asm volatile(
        "mma.sync.aligned.m16n8k8.row.col.f32.tf32.tf32.f32 "
        "{%0,%1,%2,%3}, {%4,%5,%6,%7}, {%8,%9}, {%0,%1,%2,%3};\n"
        : "+f"(c[0]), "+f"(c[1]), "+f"(c[2]), "+f"(c[3])
        : "r"(a[0]), "r"(a[1]), "r"(a[2]), "r"(a[3]), "r"(b[0]), "r"(b[1]));
}

__device__ __forceinline__ uint32_t s2u(const void* p) {
    return (uint32_t)__cvta_generic_to_shared(p);
}
__device__ __forceinline__ void cp16(uint32_t saddr, const void* g) {
    asm volatile("cp.async.cg.shared.global [%0], [%1], 16;" :: "r"(saddr), "l"(g));
}
__device__ __forceinline__ void cp_commit() {
    asm volatile("cp.async.commit_group;");
}
__device__ __forceinline__ void cp_wait0() {
    asm volatile("cp.async.wait_group 0;");
}

// ---------------------------------------------------------------------------
// tf32 GEMM with 2-stage cp.async pipeline (static smem, 37.9 KB).
// C[M,N] = A[M,K] @ B[K,N].  BM=BN=128, BK=16, 256 thr, 8 warps (2m x 4n,
// warp tile 64x32).  As raw fp32 [m][k] stride 20 (g*20 spans 8 banks ->
// conflict-free frag LDS); Bs [k][n] stride 136.  cvt.rna at fragment load
// (bit-identical fragments to the store-side-cvt version).
// ---------------------------------------------------------------------------
#define AS_S 20
#define GS   136
__device__ __forceinline__ void gemm_tf32_body(const float* __restrict__ A,
                                               const float* __restrict__ Bw,
                                               float* __restrict__ C,
                                               int N, int K) {
    __shared__ __align__(16) float As[2][128][AS_S];
    __shared__ __align__(16) float Bs[2][16][GS];

    const int bm   = blockIdx.y * 128;
    const int bn   = blockIdx.x * 128;
    const int tid  = threadIdx.x;
    const int wid  = tid >> 5;
    const int lane = tid & 31;
    const int g    = lane >> 2;
    const int t    = lane & 3;
    const int wm   = (wid >> 2) * 64;
    const int wn   = (wid & 3) * 32;

    float acc[4][4][4];
#pragma unroll
    for (int mt = 0; mt < 4; mt++)
#pragma unroll
        for (int nt = 0; nt < 4; nt++)
#pragma unroll
            for (int r = 0; r < 4; r++) acc[mt][nt][r] = 0.f;

    auto load_tile = [&](int k0, int bi) {
#pragma unroll
        for (int i = 0; i < 2; i++) {
            int f   = tid * 2 + i;
            int row = f >> 2, c4 = (f & 3) << 2;
            cp16(s2u(&As[bi][row][c4]), A + (size_t)(bm + row) * K + k0 + c4);
            int rowb = f >> 5, cb = (f & 31) << 2;
            cp16(s2u(&Bs[bi][rowb][cb]), Bw + (size_t)(k0 + rowb) * N + bn + cb);
        }
    };

    load_tile(0, 0);
    cp_commit();

    int bi = 0;
    for (int k0 = 0; k0 < K; k0 += 16, bi ^= 1) {
        cp_wait0();
        __syncthreads();
        if (k0 + 16 < K) load_tile(k0 + 16, bi ^ 1);
        cp_commit();

#pragma unroll
        for (int ks = 0; ks < 16; ks += 8) {
            uint32_t a[4][4];
#pragma unroll
            for (int mt = 0; mt < 4; mt++) {
                int m = wm + mt * 16;
                a[mt][0] = f2tf32(As[bi][m + g][ks + t]);
                a[mt][1] = f2tf32(As[bi][m + g + 8][ks + t]);
                a[mt][2] = f2tf32(As[bi][m + g][ks + t + 4]);
                a[mt][3] = f2tf32(As[bi][m + g + 8][ks + t + 4]);
            }
            uint32_t b[4][2];
#pragma unroll
            for (int nt = 0; nt < 4; nt++) {
                int n = wn + nt * 8;
                b[nt][0] = f2tf32(Bs[bi][ks + t][n + g]);
                b[nt][1] = f2tf32(Bs[bi][ks + t + 4][n + g]);
            }
#pragma unroll
            for (int mt = 0; mt < 4; mt++)
#pragma unroll
                for (int nt = 0; nt < 4; nt++)
                    mma_tf32(acc[mt][nt], a[mt], b[nt]);
        }
    }

#pragma unroll
    for (int mt = 0; mt < 4; mt++) {
#pragma unroll
        for (int nt = 0; nt < 4; nt++) {
            int r0 = bm + wm + mt * 16 + g;
            int cc = bn + wn + nt * 8 + 2 * t;
            *(float2*)(C + (size_t)r0 * N + cc)       = make_float2(acc[mt][nt][0], acc[mt][nt][1]);
            *(float2*)(C + (size_t)(r0 + 8) * N + cc) = make_float2(acc[mt][nt][2], acc[mt][nt][3]);
        }
    }
}

__global__ __launch_bounds__(256) void gemm_qkv_kernel(const float* __restrict__ x,
                                                       const float* __restrict__ W) {
    gemm_tf32_body(x, W, g_qkv, 3 * DIM, DIM);
}
__global__ __launch_bounds__(256) void gemm_proj_kernel(const float* __restrict__ W,
                                                        float* __restrict__ out) {
    gemm_tf32_body(g_o, W, out, DIM, DIM);
}

// ---------------------------------------------------------------------------
// RoPE + split/transpose
// ---------------------------------------------------------------------------
__global__ __launch_bounds__(256) void rope_split_kernel(const float* __restrict__ fcos,
                                                         const float* __restrict__ fsin) {
    int idx = blockIdx.x * 256 + threadIdx.x;
    int row = idx >> 9;
    int rem = idx & 511;
    int h   = rem >> 5;
    int i   = rem & 31;
    int t   = row & (TT - 1);
    int b   = row >> 11;

    float c = fcos[t * (HD / 2) + i];
    float s = fsin[t * (HD / 2) + i];

    const float* base = g_qkv + (size_t)row * (3 * DIM) + h * HD + 2 * i;
    float2 q = *(const float2*)(base);
    float2 k = *(const float2*)(base + DIM);
    float2 v = *(const float2*)(base + 2 * DIM);

    size_t dst = ((size_t)(b * NH + h) * TT + t) * HD + 2 * i;
    *(float2*)(g_q + dst) = make_float2(q.x * c - q.y * s, q.x * s + q.y * c);
    *(float2*)(g_k + dst) = make_float2(k.x * c - k.y * s, k.x * s + k.y * c);
    *(float2*)(g_v + dst) = v;
}

// ---------------------------------------------------------------------------
// Flash attention with tf32 mma (round-3 body — known passing).
// 256 thr / 8 warps, 128 q rows (16/warp), KV tile 64, static smem 35 KB.
// Ks stride 68, Vs stride 72: conflict-free B-frag LDS.
// ---------------------------------------------------------------------------
#define KS_S 68
#define VS_S 72
__global__ __launch_bounds__(256, 1) void attn_kernel() {
    __shared__ __align__(16) float Ks[64][KS_S];
    __shared__ __align__(16) float Vs[64][VS_S];

    const int bh   = blockIdx.y;
    const int q0   = blockIdx.x * 128;
    const int tid  = threadIdx.x;
    const int wid  = tid >> 5;
    const int lane = tid & 31;
    const int g    = lane >> 2;
    const int t    = lane & 3;

    const size_t qbase = ((size_t)bh * TT + q0 + wid * 16) * HD;
    uint32_t qa[8][4];
#pragma unroll
    for (int kt = 0; kt < 8; kt++) {
        qa[kt][0] = f2tf32(g_q[qbase + (size_t)g * HD + kt * 8 + t] * 0.125f);
        qa[kt][1] = f2tf32(g_q[qbase + (size_t)(g + 8) * HD + kt * 8 + t] * 0.125f);
        qa[kt][2] = f2tf32(g_q[qbase + (size_t)g * HD + kt * 8 + t + 4] * 0.125f);
        qa[kt][3] = f2tf32(g_q[qbase + (size_t)(g + 8) * HD + kt * 8 + t + 4] * 0.125f);
    }

    float O[8][4];
#pragma unroll
    for (int nt = 0; nt < 8; nt++)
#pragma unroll
        for (int r = 0; r < 4; r++) O[nt][r] = 0.f;
    float m0 = -1e30f, m1 = -1e30f, l0 = 0.f, l1 = 0.f;

    for (int kv0 = 0; kv0 < TT; kv0 += 64) {
        const float* Kg = g_k + ((size_t)bh * TT + kv0) * HD;
        const float* Vg = g_v + ((size_t)bh * TT + kv0) * HD;
#pragma unroll
        for (int i = 0; i < 4; i++) {
            int idx = tid + i * 256;
            int row = idx >> 4, c4 = (idx & 15) << 2;
            float4 kv = *(const float4*)(Kg + (size_t)row * HD + c4);
            Ks[row][c4 + 0] = __uint_as_float(f2tf32(kv.x));
            Ks[row][c4 + 1] = __uint_as_float(f2tf32(kv.y));
            Ks[row][c4 + 2] = __uint_as_float(f2tf32(kv.z));
            Ks[row][c4 + 3] = __uint_as_float(f2tf32(kv.w));
            float4 vv = *(const float4*)(Vg + (size_t)row * HD + c4);
            Vs[row][c4 + 0] = __uint_as_float(f2tf32(vv.x));
            Vs[row][c4 + 1] = __uint_as_float(f2tf32(vv.y));
            Vs[row][c4 + 2] = __uint_as_float(f2tf32(vv.z));
            Vs[row][c4 + 3] = __uint_as_float(f2tf32(vv.w));
        }
        __syncthreads();

        float s[8][4];
#pragma unroll
        for (int nt = 0; nt < 8; nt++)
#pragma unroll
            for (int r = 0; r < 4; r++) s[nt][r] = 0.f;
#pragma unroll
        for (int kt = 0; kt < 8; kt++) {
            uint32_t kb[8][2];
#pragma unroll
            for (int nt = 0; nt < 8; nt++) {
                kb[nt][0] = __float_as_uint(Ks[nt * 8 + g][kt * 8 + t]);
                kb[nt][1] = __float_as_uint(Ks[nt * 8 + g][kt * 8 + t + 4]);
            }
#pragma unroll
            for (int nt = 0; nt < 8; nt++)
                mma_tf32(s[nt], qa[kt], kb[nt]);
        }

        float mx0 = -1e30f, mx1 = -1e30f;
#pragma unroll
        for (int nt = 0; nt < 8; nt++) {
            mx0 = fmaxf(mx0, fmaxf(s[nt][0], s[nt][1]));
            mx1 = fmaxf(mx1, fmaxf(s[nt][2], s[nt][3]));
        }
        mx0 = fmaxf(mx0, __shfl_xor_sync(0xffffffffu, mx0, 1));
        mx0 = fmaxf(mx0, __shfl_xor_sync(0xffffffffu, mx0, 2));
        mx1 = fmaxf(mx1, __shfl_xor_sync(0xffffffffu, mx1, 1));
        mx1 = fmaxf(mx1, __shfl_xor_sync(0xffffffffu, mx1, 2));
        float nm0 = fmaxf(m0, mx0), nm1 = fmaxf(m1, mx1);
        float c0 = __expf(m0 - nm0), c1 = __expf(m1 - nm1);
        m0 = nm0; m1 = nm1;
        l0 *= c0;  l1 *= c1;
#pragma unroll
        for (int nt = 0; nt < 8; nt++) {
            O[nt][0] *= c0; O[nt][1] *= c0;
            O[nt][2] *= c1; O[nt][3] *= c1;
        }
        uint32_t p[8][4];
#pragma unroll
        for (int nt = 0; nt < 8; nt++) {
            float e0 = __expf(s[nt][0] - m0);
            float e1 = __expf(s[nt][1] - m0);
            float e2 = __expf(s[nt][2] - m1);
            float e3 = __expf(s[nt][3] - m1);
            l0 += e0 + e1;  l1 += e2 + e3;
            p[nt][0] = f2tf32(e0); p[nt][1] = f2tf32(e1);
            p[nt][2] = f2tf32(e2); p[nt][3] = f2tf32(e3);
        }

#pragma unroll
        for (int kt = 0; kt < 8; kt++) {
            int base = lane & 28;
            int src0 = base + (t >> 1);
            int src1 = base + (t >> 1) + 2;
            uint32_t x00 = __shfl_sync(0xffffffffu, p[kt][0], src0);
            uint32_t x01 = __shfl_sync(0xffffffffu, p[kt][1], src0);
            uint32_t x02 = __shfl_sync(0xffffffffu, p[kt][2], src0);
            uint32_t x03 = __shfl_sync(0xffffffffu, p[kt][3], src0);
            uint32_t x10 = __shfl_sync(0xffffffffu, p[kt][0], src1);
            uint32_t x11 = __shfl_sync(0xffffffffu, p[kt][1], src1);
            uint32_t x12 = __shfl_sync(0xffffffffu, p[kt][2], src1);
            uint32_t x13 = __shfl_sync(0xffffffffu, p[kt][3], src1);
            uint32_t pa[4];
            pa[0] = (t & 1) ? x01 : x00;
            pa[1] = (t & 1) ? x03 : x02;
            pa[2] = (t & 1) ? x11 : x10;
            pa[3] = (t & 1) ? x13 : x12;
#pragma unroll
            for (int nt = 0; nt < 8; nt++) {
                uint32_t vb[2];
                vb[0] = __float_as_uint(Vs[kt * 8 + t][nt * 8 + g]);
                vb[1] = __float_as_uint(Vs[kt * 8 + t + 4][nt * 8 + g]);
                mma_tf32(O[nt], pa, vb);
            }
        }
        __syncthreads();
    }

    l0 += __shfl_xor_sync(0xffffffffu, l0, 1);
    l0 += __shfl_xor_sync(0xffffffffu, l0, 2);
    l1 += __shfl_xor_sync(0xffffffffu, l1, 1);
    l1 += __shfl_xor_sync(0xffffffffu, l1, 2);
    float inv0 = 1.f / l0, inv1 = 1.f / l1;

    int b = bh >> 4, h = bh & 15;
    int r0 = q0 + wid * 16 + g;
#pragma unroll
    for (int nt = 0; nt < 8; nt++) {
        int cc = h * HD + nt * 8 + 2 * t;
        *(float2*)(g_o + ((size_t)(b * TT + r0)) * DIM + cc) =
            make_float2(O[nt][0] * inv0, O[nt][1] * inv0);
        *(float2*)(g_o + ((size_t)(b * TT + r0 + 8)) * DIM + cc) =
            make_float2(O[nt][2] * inv1, O[nt][3] * inv1);
    }
}

// ---------------------------------------------------------------------------
// Launch
// ---------------------------------------------------------------------------
extern "C" void kernel_launch(void* const* d_in, const int* in_sizes, int n_in,
                              void* d_out, int out_size) {
    (void)in_sizes; (void)n_in; (void)out_size;
    const float* x     = (const float*)d_in[0];
    const float* fcos  = (const float*)d_in[1];
    const float* fsin  = (const float*)d_in[2];
    const float* Wqkv  = (const float*)d_in[4];
    const float* Wproj = (const float*)d_in[5];
    float* out = (float*)d_out;

    {
        dim3 grid(3 * DIM / 128, MROWS / 128);
        gemm_qkv_kernel<<<grid, 256>>>(x, Wqkv);
    }
    {
        int total = MROWS * (NH * HD / 2);
        rope_split_kernel<<<total / 256, 256>>>(fcos, fsin);
    }
    {
        dim3 grid(TT / 128, BB * NH);
        attn_kernel<<<grid, 256>>>();
    }
    {
        dim3 grid(DIM / 128, MROWS / 128);
        gemm_proj_kernel<<<grid, 256>>>(Wproj, out);
    }
}

// round 7
// speedup vs baseline: 3.2922x; 1.0245x over previous
#include <cuda_runtime.h>
#include <cstdint>

#define BB   4
#define TT   2048
#define DIM  1024
#define NH   16
#define HD   64
#define MROWS (BB*TT)          // 8192

// ---------------------------------------------------------------------------
// Scratch
// ---------------------------------------------------------------------------
__device__ float g_qkv[(size_t)MROWS * 3 * DIM];
__device__ float g_q[(size_t)MROWS * DIM];          // [b,h,t,d]  tf32-rounded, pre-scaled
__device__ float g_k[(size_t)MROWS * DIM];          // tf32-rounded
__device__ float g_v[(size_t)MROWS * DIM];          // tf32-rounded
__device__ float g_o[(size_t)MROWS * DIM];          // [b,t,h*d]  tf32-rounded
__device__ float g_xc[(size_t)MROWS * DIM];         // tf32(x)
__device__ float g_wqkvc[(size_t)DIM * 3 * DIM];    // tf32(Wqkv)
__device__ float g_wprojc[(size_t)DIM * DIM];       // tf32(Wproj)

// ---------------------------------------------------------------------------
// helpers
// ---------------------------------------------------------------------------
__device__ __forceinline__ uint32_t f2tf32(float x) {
    uint32_t r;
    asm("cvt.rna.tf32.f32 %0, %1;" : "=r"(r) : "f"(x));
    return r;
}
__device__ __forceinline__ float f2tf32f(float x) {
    return __uint_as_float(f2tf32(x));
}

__device__ __forceinline__ void mma_tf32(float c[4], const uint32_t a[4],
                                         const uint32_t b[2]) {
    asm volatile(
        "mma.sync.aligned.m16n8k8.row.col.f32.tf32.tf32.f32 "
        "{%0,%1,%2,%3}, {%4,%5,%6,%7}, {%8,%9}, {%0,%1,%2,%3};\n"
        : "+f"(c[0]), "+f"(c[1]), "+f"(c[2]), "+f"(c[3])
        : "r"(a[0]), "r"(a[1]), "r"(a[2]), "r"(a[3]), "r"(b[0]), "r"(b[1]));
}

__device__ __forceinline__ uint32_t s2u(const void* p) {
    return (uint32_t)__cvta_generic_to_shared(p);
}
__device__ __forceinline__ void cp16(uint32_t saddr, const void* g) {
    asm volatile("cp.async.cg.shared.global [%0], [%1], 16;" :: "r"(saddr), "l"(g));
}
__device__ __forceinline__ void cp_commit() {
    asm volatile("cp.async.commit_group;");
}
__device__ __forceinline__ void cp_wait0() {
    asm volatile("cp.async.wait_group 0;");
}

// ---------------------------------------------------------------------------
// tf32 pre-round pass (elementwise, float4)
// ---------------------------------------------------------------------------
__global__ __launch_bounds__(256) void tf32_cvt_kernel(const float4* __restrict__ in,
                                                       float4* __restrict__ out, int n4) {
    int i = blockIdx.x * 256 + threadIdx.x;
    if (i < n4) {
        float4 v = in[i];
        v.x = f2tf32f(v.x); v.y = f2tf32f(v.y);
        v.z = f2tf32f(v.z); v.w = f2tf32f(v.w);
        out[i] = v;
    }
}

// ---------------------------------------------------------------------------
// tf32 GEMM, 2-stage cp.async pipeline, inputs pre-rounded (NO cvt in loop).
// C[M,N] = A[M,K] @ B[K,N].  BM=BN=128, BK=16, 256 thr, 8 warps (2m x 4n).
// As [m][k] stride 20; Bs [k][n] stride 136.
// ---------------------------------------------------------------------------
#define AS_S 20
#define GS   136
__device__ __forceinline__ void gemm_tf32_body(const float* __restrict__ A,
                                               const float* __restrict__ Bw,
                                               float* __restrict__ C,
                                               int N, int K) {
    __shared__ __align__(16) float As[2][128][AS_S];
    __shared__ __align__(16) float Bs[2][16][GS];

    const int bm   = blockIdx.y * 128;
    const int bn   = blockIdx.x * 128;
    const int tid  = threadIdx.x;
    const int wid  = tid >> 5;
    const int lane = tid & 31;
    const int g    = lane >> 2;
    const int t    = lane & 3;
    const int wm   = (wid >> 2) * 64;
    const int wn   = (wid & 3) * 32;

    float acc[4][4][4];
#pragma unroll
    for (int mt = 0; mt < 4; mt++)
#pragma unroll
        for (int nt = 0; nt < 4; nt++)
#pragma unroll
            for (int r = 0; r < 4; r++) acc[mt][nt][r] = 0.f;

    auto load_tile = [&](int k0, int bi) {
#pragma unroll
        for (int i = 0; i < 2; i++) {
            int f   = tid * 2 + i;
            int row = f >> 2, c4 = (f & 3) << 2;
            cp16(s2u(&As[bi][row][c4]), A + (size_t)(bm + row) * K + k0 + c4);
            int rowb = f >> 5, cb = (f & 31) << 2;
            cp16(s2u(&Bs[bi][rowb][cb]), Bw + (size_t)(k0 + rowb) * N + bn + cb);
        }
    };

    load_tile(0, 0);
    cp_commit();

    int bi = 0;
    for (int k0 = 0; k0 < K; k0 += 16, bi ^= 1) {
        cp_wait0();
        __syncthreads();
        if (k0 + 16 < K) load_tile(k0 + 16, bi ^ 1);
        cp_commit();

#pragma unroll
        for (int ks = 0; ks < 16; ks += 8) {
            uint32_t a[4][4];
#pragma unroll
            for (int mt = 0; mt < 4; mt++) {
                int m = wm + mt * 16;
                a[mt][0] = __float_as_uint(As[bi][m + g][ks + t]);
                a[mt][1] = __float_as_uint(As[bi][m + g + 8][ks + t]);
                a[mt][2] = __float_as_uint(As[bi][m + g][ks + t + 4]);
                a[mt][3] = __float_as_uint(As[bi][m + g + 8][ks + t + 4]);
            }
            uint32_t b[4][2];
#pragma unroll
            for (int nt = 0; nt < 4; nt++) {
                int n = wn + nt * 8;
                b[nt][0] = __float_as_uint(Bs[bi][ks + t][n + g]);
                b[nt][1] = __float_as_uint(Bs[bi][ks + t + 4][n + g]);
            }
#pragma unroll
            for (int mt = 0; mt < 4; mt++)
#pragma unroll
                for (int nt = 0; nt < 4; nt++)
                    mma_tf32(acc[mt][nt], a[mt], b[nt]);
        }
    }

#pragma unroll
    for (int mt = 0; mt < 4; mt++) {
#pragma unroll
        for (int nt = 0; nt < 4; nt++) {
            int r0 = bm + wm + mt * 16 + g;
            int cc = bn + wn + nt * 8 + 2 * t;
            *(float2*)(C + (size_t)r0 * N + cc)       = make_float2(acc[mt][nt][0], acc[mt][nt][1]);
            *(float2*)(C + (size_t)(r0 + 8) * N + cc) = make_float2(acc[mt][nt][2], acc[mt][nt][3]);
        }
    }
}

__global__ __launch_bounds__(256) void gemm_qkv_kernel() {
    gemm_tf32_body(g_xc, g_wqkvc, g_qkv, 3 * DIM, DIM);
}
__global__ __launch_bounds__(256) void gemm_proj_kernel(float* __restrict__ out) {
    gemm_tf32_body(g_o, g_wprojc, out, DIM, DIM);
}

// ---------------------------------------------------------------------------
// RoPE + split/transpose.  Writes tf32-rounded values; Q pre-scaled by 0.125.
// ---------------------------------------------------------------------------
__global__ __launch_bounds__(256) void rope_split_kernel(const float* __restrict__ fcos,
                                                         const float* __restrict__ fsin) {
    int idx = blockIdx.x * 256 + threadIdx.x;
    int row = idx >> 9;
    int rem = idx & 511;
    int h   = rem >> 5;
    int i   = rem & 31;
    int t   = row & (TT - 1);
    int b   = row >> 11;

    float c = fcos[t * (HD / 2) + i];
    float s = fsin[t * (HD / 2) + i];

    const float* base = g_qkv + (size_t)row * (3 * DIM) + h * HD + 2 * i;
    float2 q = *(const float2*)(base);
    float2 k = *(const float2*)(base + DIM);
    float2 v = *(const float2*)(base + 2 * DIM);

    size_t dst = ((size_t)(b * NH + h) * TT + t) * HD + 2 * i;
    *(float2*)(g_q + dst) = make_float2(f2tf32f((q.x * c - q.y * s) * 0.125f),
                                        f2tf32f((q.x * s + q.y * c) * 0.125f));
    *(float2*)(g_k + dst) = make_float2(f2tf32f(k.x * c - k.y * s),
                                        f2tf32f(k.x * s + k.y * c));
    *(float2*)(g_v + dst) = make_float2(f2tf32f(v.x), f2tf32f(v.y));
}

// ---------------------------------------------------------------------------
// Flash attention, tf32 mma.  Inputs pre-rounded -> raw cp.async KV loads,
// no cvt on fragment loads (only P=exp needs cvt).  Static smem 35 KB.
// 256 thr / 8 warps, 128 q rows (16/warp), KV tile 64.
// ---------------------------------------------------------------------------
#define KS_S 68
#define VS_S 72
__global__ __launch_bounds__(256, 1) void attn_kernel() {
    __shared__ __align__(16) float Ks[64][KS_S];
    __shared__ __align__(16) float Vs[64][VS_S];

    const int bh   = blockIdx.y;
    const int q0   = blockIdx.x * 128;
    const int tid  = threadIdx.x;
    const int wid  = tid >> 5;
    const int lane = tid & 31;
    const int g    = lane >> 2;
    const int t    = lane & 3;

    const float* Kbase = g_k + (size_t)bh * TT * HD;
    const float* Vbase = g_v + (size_t)bh * TT * HD;

    // Q fragments: already tf32-rounded and pre-scaled
    const size_t qbase = ((size_t)bh * TT + q0 + wid * 16) * HD;
    uint32_t qa[8][4];
#pragma unroll
    for (int kt = 0; kt < 8; kt++) {
        qa[kt][0] = __float_as_uint(g_q[qbase + (size_t)g * HD + kt * 8 + t]);
        qa[kt][1] = __float_as_uint(g_q[qbase + (size_t)(g + 8) * HD + kt * 8 + t]);
        qa[kt][2] = __float_as_uint(g_q[qbase + (size_t)g * HD + kt * 8 + t + 4]);
        qa[kt][3] = __float_as_uint(g_q[qbase + (size_t)(g + 8) * HD + kt * 8 + t + 4]);
    }

    float O[8][4];
#pragma unroll
    for (int nt = 0; nt < 8; nt++)
#pragma unroll
        for (int r = 0; r < 4; r++) O[nt][r] = 0.f;
    float m0 = -1e30f, m1 = -1e30f, l0 = 0.f, l1 = 0.f;

    for (int kv0 = 0; kv0 < TT; kv0 += 64) {
        // raw async copy of K/V tiles (pre-rounded in gmem)
#pragma unroll
        for (int i = 0; i < 4; i++) {
            int idx = tid + i * 256;
            int row = idx >> 4, c4 = (idx & 15) << 2;
            cp16(s2u(&Ks[row][c4]), Kbase + (size_t)(kv0 + row) * HD + c4);
            cp16(s2u(&Vs[row][c4]), Vbase + (size_t)(kv0 + row) * HD + c4);
        }
        cp_commit();
        cp_wait0();
        __syncthreads();

        // S = Q @ K^T : warp computes [16 x 64]
        float s[8][4];
#pragma unroll
        for (int nt = 0; nt < 8; nt++)
#pragma unroll
            for (int r = 0; r < 4; r++) s[nt][r] = 0.f;
#pragma unroll
        for (int kt = 0; kt < 8; kt++) {
            uint32_t kb[8][2];
#pragma unroll
            for (int nt = 0; nt < 8; nt++) {
                kb[nt][0] = __float_as_uint(Ks[nt * 8 + g][kt * 8 + t]);
                kb[nt][1] = __float_as_uint(Ks[nt * 8 + g][kt * 8 + t + 4]);
            }
#pragma unroll
            for (int nt = 0; nt < 8; nt++)
                mma_tf32(s[nt], qa[kt], kb[nt]);
        }

        // online softmax
        float mx0 = -1e30f, mx1 = -1e30f;
#pragma unroll
        for (int nt = 0; nt < 8; nt++) {
            mx0 = fmaxf(mx0, fmaxf(s[nt][0], s[nt][1]));
            mx1 = fmaxf(mx1, fmaxf(s[nt][2], s[nt][3]));
        }
        mx0 = fmaxf(mx0, __shfl_xor_sync(0xffffffffu, mx0, 1));
        mx0 = fmaxf(mx0, __shfl_xor_sync(0xffffffffu, mx0, 2));
        mx1 = fmaxf(mx1, __shfl_xor_sync(0xffffffffu, mx1, 1));
        mx1 = fmaxf(mx1, __shfl_xor_sync(0xffffffffu, mx1, 2));
        float nm0 = fmaxf(m0, mx0), nm1 = fmaxf(m1, mx1);
        float c0 = __expf(m0 - nm0), c1 = __expf(m1 - nm1);
        m0 = nm0; m1 = nm1;
        l0 *= c0;  l1 *= c1;
#pragma unroll
        for (int nt = 0; nt < 8; nt++) {
            O[nt][0] *= c0; O[nt][1] *= c0;
            O[nt][2] *= c1; O[nt][3] *= c1;
        }
        uint32_t p[8][4];
#pragma unroll
        for (int nt = 0; nt < 8; nt++) {
            float e0 = __expf(s[nt][0] - m0);
            float e1 = __expf(s[nt][1] - m0);
            float e2 = __expf(s[nt][2] - m1);
            float e3 = __expf(s[nt][3] - m1);
            l0 += e0 + e1;  l1 += e2 + e3;
            p[nt][0] = f2tf32(e0); p[nt][1] = f2tf32(e1);
            p[nt][2] = f2tf32(e2); p[nt][3] = f2tf32(e3);
        }

        // O += P @ V.  P C-layout -> A-layout via shuffles.
#pragma unroll
        for (int kt = 0; kt < 8; kt++) {
            int base = lane & 28;
            int src0 = base + (t >> 1);
            int src1 = base + (t >> 1) + 2;
            uint32_t x00 = __shfl_sync(0xffffffffu, p[kt][0], src0);
            uint32_t x01 = __shfl_sync(0xffffffffu, p[kt][1], src0);
            uint32_t x02 = __shfl_sync(0xffffffffu, p[kt][2], src0);
            uint32_t x03 = __shfl_sync(0xffffffffu, p[kt][3], src0);
            uint32_t x10 = __shfl_sync(0xffffffffu, p[kt][0], src1);
            uint32_t x11 = __shfl_sync(0xffffffffu, p[kt][1], src1);
            uint32_t x12 = __shfl_sync(0xffffffffu, p[kt][2], src1);
            uint32_t x13 = __shfl_sync(0xffffffffu, p[kt][3], src1);
            uint32_t pa[4];
            pa[0] = (t & 1) ? x01 : x00;
            pa[1] = (t & 1) ? x03 : x02;
            pa[2] = (t & 1) ? x11 : x10;
            pa[3] = (t & 1) ? x13 : x12;
#pragma unroll
            for (int nt = 0; nt < 8; nt++) {
                uint32_t vb[2];
                vb[0] = __float_as_uint(Vs[kt * 8 + t][nt * 8 + g]);
                vb[1] = __float_as_uint(Vs[kt * 8 + t + 4][nt * 8 + g]);
                mma_tf32(O[nt], pa, vb);
            }
        }
        __syncthreads();
    }

    // final normalize + tf32-round + write to g_o [b, t, h*d]
    l0 += __shfl_xor_sync(0xffffffffu, l0, 1);
    l0 += __shfl_xor_sync(0xffffffffu, l0, 2);
    l1 += __shfl_xor_sync(0xffffffffu, l1, 1);
    l1 += __shfl_xor_sync(0xffffffffu, l1, 2);
    float inv0 = 1.f / l0, inv1 = 1.f / l1;

    int b = bh >> 4, h = bh & 15;
    int r0 = q0 + wid * 16 + g;
#pragma unroll
    for (int nt = 0; nt < 8; nt++) {
        int cc = h * HD + nt * 8 + 2 * t;
        *(float2*)(g_o + ((size_t)(b * TT + r0)) * DIM + cc) =
            make_float2(f2tf32f(O[nt][0] * inv0), f2tf32f(O[nt][1] * inv0));
        *(float2*)(g_o + ((size_t)(b * TT + r0 + 8)) * DIM + cc) =
            make_float2(f2tf32f(O[nt][2] * inv1), f2tf32f(O[nt][3] * inv1));
    }
}

// ---------------------------------------------------------------------------
// Launch
// ---------------------------------------------------------------------------
extern "C" void kernel_launch(void* const* d_in, const int* in_sizes, int n_in,
                              void* d_out, int out_size) {
    (void)in_sizes; (void)n_in; (void)out_size;
    const float* x     = (const float*)d_in[0];
    const float* fcos  = (const float*)d_in[1];
    const float* fsin  = (const float*)d_in[2];
    const float* Wqkv  = (const float*)d_in[4];
    const float* Wproj = (const float*)d_in[5];
    float* out = (float*)d_out;

    float* xc;   cudaGetSymbolAddress((void**)&xc,   g_xc);
    float* wqc;  cudaGetSymbolAddress((void**)&wqc,  g_wqkvc);
    float* wpc;  cudaGetSymbolAddress((void**)&wpc,  g_wprojc);

    // tf32 pre-round passes
    {
        int n4 = MROWS * DIM / 4;                       // 2M
        tf32_cvt_kernel<<<n4 / 256, 256>>>((const float4*)x, (float4*)xc, n4);
    }
    {
        int n4 = DIM * 3 * DIM / 4;                     // 768K
        tf32_cvt_kernel<<<n4 / 256, 256>>>((const float4*)Wqkv, (float4*)wqc, n4);
    }
    {
        int n4 = DIM * DIM / 4;                         // 256K
        tf32_cvt_kernel<<<n4 / 256, 256>>>((const float4*)Wproj, (float4*)wpc, n4);
    }

    {
        dim3 grid(3 * DIM / 128, MROWS / 128);
        gemm_qkv_kernel<<<grid, 256>>>();
    }
    {
        int total = MROWS * (NH * HD / 2);
        rope_split_kernel<<<total / 256, 256>>>(fcos, fsin);
    }
    {
        dim3 grid(TT / 128, BB * NH);
        attn_kernel<<<grid, 256>>>();
    }
    {
        dim3 grid(DIM / 128, MROWS / 128);
        gemm_proj_kernel<<<grid, 256>>>(out);
    }
}

// round 8
// speedup vs baseline: 3.5443x; 1.0766x over previous
#include <cuda_runtime.h>
#include <cstdint>

#define BB   4
#define TT   2048
#define DIM  1024
#define NH   16
#define HD   64
#define MROWS (BB*TT)          // 8192

// ---------------------------------------------------------------------------
// Scratch
// ---------------------------------------------------------------------------
__device__ float g_q[(size_t)MROWS * DIM];          // [b,h,t,d]  tf32-rounded, pre-scaled
__device__ float g_k[(size_t)MROWS * DIM];          // [b,h,t,d]  tf32-rounded
__device__ float g_v[(size_t)MROWS * DIM];          // [b,h,t,d]  tf32-rounded
__device__ float g_o[(size_t)MROWS * DIM];          // [b,t,h*d]  tf32-rounded
__device__ float g_xc[(size_t)MROWS * DIM];         // tf32(x)
__device__ float g_wqkvc[(size_t)DIM * 3 * DIM];    // tf32(Wqkv)
__device__ float g_wprojc[(size_t)DIM * DIM];       // tf32(Wproj)

// ---------------------------------------------------------------------------
// helpers
// ---------------------------------------------------------------------------
__device__ __forceinline__ uint32_t f2tf32(float x) {
    uint32_t r;
    asm("cvt.rna.tf32.f32 %0, %1;" : "=r"(r) : "f"(x));
    return r;
}
__device__ __forceinline__ float f2tf32f(float x) {
    return __uint_as_float(f2tf32(x));
}

__device__ __forceinline__ void mma_tf32(float c[4], const uint32_t a[4],
                                         const uint32_t b[2]) {
    asm volatile(
        "mma.sync.aligned.m16n8k8.row.col.f32.tf32.tf32.f32 "
        "{%0,%1,%2,%3}, {%4,%5,%6,%7}, {%8,%9}, {%0,%1,%2,%3};\n"
        : "+f"(c[0]), "+f"(c[1]), "+f"(c[2]), "+f"(c[3])
        : "r"(a[0]), "r"(a[1]), "r"(a[2]), "r"(a[3]), "r"(b[0]), "r"(b[1]));
}

__device__ __forceinline__ uint32_t s2u(const void* p) {
    return (uint32_t)__cvta_generic_to_shared(p);
}
__device__ __forceinline__ void cp16(uint32_t saddr, const void* g) {
    asm volatile("cp.async.cg.shared.global [%0], [%1], 16;" :: "r"(saddr), "l"(g));
}
__device__ __forceinline__ void cp_commit() {
    asm volatile("cp.async.commit_group;");
}
__device__ __forceinline__ void cp_wait0() {
    asm volatile("cp.async.wait_group 0;");
}

// ---------------------------------------------------------------------------
// tf32 pre-round pass (elementwise, float4)
// ---------------------------------------------------------------------------
__global__ __launch_bounds__(256) void tf32_cvt_kernel(const float4* __restrict__ in,
                                                       float4* __restrict__ out, int n4) {
    int i = blockIdx.x * 256 + threadIdx.x;
    if (i < n4) {
        float4 v = in[i];
        v.x = f2tf32f(v.x); v.y = f2tf32f(v.y);
        v.z = f2tf32f(v.z); v.w = f2tf32f(v.w);
        out[i] = v;
    }
}

// ---------------------------------------------------------------------------
// tf32 GEMM mainloop, 2-stage cp.async pipeline, inputs pre-rounded.
// BM=BN=128, BK=16, 256 thr, 8 warps (2m x 4n, warp tile 64x32).
// As [m][k] stride 20; Bs [k][n] stride 136.
// ---------------------------------------------------------------------------
#define AS_S 20
#define GS   136
__device__ __forceinline__ void gemm_mainloop(const float* __restrict__ A,
                                              const float* __restrict__ Bw,
                                              int N, int K,
                                              int bm, int bn,
                                              float acc[4][4][4]) {
    __shared__ __align__(16) float As[2][128][AS_S];
    __shared__ __align__(16) float Bs[2][16][GS];

    const int tid  = threadIdx.x;
    const int wid  = tid >> 5;
    const int lane = tid & 31;
    const int g    = lane >> 2;
    const int t    = lane & 3;
    const int wm   = (wid >> 2) * 64;
    const int wn   = (wid & 3) * 32;

#pragma unroll
    for (int mt = 0; mt < 4; mt++)
#pragma unroll
        for (int nt = 0; nt < 4; nt++)
#pragma unroll
            for (int r = 0; r < 4; r++) acc[mt][nt][r] = 0.f;

    auto load_tile = [&](int k0, int bi) {
#pragma unroll
        for (int i = 0; i < 2; i++) {
            int f   = tid * 2 + i;
            int row = f >> 2, c4 = (f & 3) << 2;
            cp16(s2u(&As[bi][row][c4]), A + (size_t)(bm + row) * K + k0 + c4);
            int rowb = f >> 5, cb = (f & 31) << 2;
            cp16(s2u(&Bs[bi][rowb][cb]), Bw + (size_t)(k0 + rowb) * N + bn + cb);
        }
    };

    load_tile(0, 0);
    cp_commit();

    int bi = 0;
    for (int k0 = 0; k0 < K; k0 += 16, bi ^= 1) {
        cp_wait0();
        __syncthreads();
        if (k0 + 16 < K) load_tile(k0 + 16, bi ^ 1);
        cp_commit();

#pragma unroll
        for (int ks = 0; ks < 16; ks += 8) {
            uint32_t a[4][4];
#pragma unroll
            for (int mt = 0; mt < 4; mt++) {
                int m = wm + mt * 16;
                a[mt][0] = __float_as_uint(As[bi][m + g][ks + t]);
                a[mt][1] = __float_as_uint(As[bi][m + g + 8][ks + t]);
                a[mt][2] = __float_as_uint(As[bi][m + g][ks + t + 4]);
                a[mt][3] = __float_as_uint(As[bi][m + g + 8][ks + t + 4]);
            }
            uint32_t b[4][2];
#pragma unroll
            for (int nt = 0; nt < 4; nt++) {
                int n = wn + nt * 8;
                b[nt][0] = __float_as_uint(Bs[bi][ks + t][n + g]);
                b[nt][1] = __float_as_uint(Bs[bi][ks + t + 4][n + g]);
            }
#pragma unroll
            for (int mt = 0; mt < 4; mt++)
#pragma unroll
                for (int nt = 0; nt < 4; nt++)
                    mma_tf32(acc[mt][nt], a[mt], b[nt]);
        }
    }
}

// ---------------------------------------------------------------------------
// QKV GEMM with fused RoPE + split epilogue.
// C-frag regs {0,1} hold cols (2t, 2t+1) = an (even, odd) RoPE pair.
// Writes tf32-rounded Q (pre-scaled 0.125) / K / V in [b,h,t,d] layout —
// bit-identical to the old rope_split output.
// ---------------------------------------------------------------------------
__global__ __launch_bounds__(256) void gemm_qkv_kernel(const float* __restrict__ fcos,
                                                       const float* __restrict__ fsin) {
    const int bm = blockIdx.y * 128;
    const int bn = blockIdx.x * 128;
    float acc[4][4][4];
    gemm_mainloop(g_xc, g_wqkvc, 3 * DIM, DIM, bm, bn, acc);

    const int tid  = threadIdx.x;
    const int wid  = tid >> 5;
    const int lane = tid & 31;
    const int g    = lane >> 2;
    const int t    = lane & 3;
    const int wm   = (wid >> 2) * 64;
    const int wn   = (wid & 3) * 32;

#pragma unroll
    for (int mt = 0; mt < 4; mt++) {
#pragma unroll
        for (int half = 0; half < 2; half++) {
            int r  = bm + wm + mt * 16 + g + half * 8;
            int b  = r >> 11;
            int tt = r & (TT - 1);
#pragma unroll
            for (int nt = 0; nt < 4; nt++) {
                int col    = bn + wn + nt * 8 + 2 * t;
                int region = col >> 10;            // 0=Q, 1=K, 2=V (uniform per block)
                int cr     = col & 1023;
                int h      = cr >> 6;
                int d      = cr & 63;              // even
                float e = acc[mt][nt][half * 2];
                float o = acc[mt][nt][half * 2 + 1];
                size_t dst = (((size_t)(b * NH + h) * TT + tt) * HD + d);
                if (region == 2) {
                    *(float2*)(g_v + dst) = make_float2(f2tf32f(e), f2tf32f(o));
                } else {
                    float c = fcos[tt * (HD / 2) + (d >> 1)];
                    float s = fsin[tt * (HD / 2) + (d >> 1)];
                    float e2 = e * c - o * s;
                    float o2 = e * s + o * c;
                    if (region == 0) {
                        *(float2*)(g_q + dst) =
                            make_float2(f2tf32f(e2 * 0.125f), f2tf32f(o2 * 0.125f));
                    } else {
                        *(float2*)(g_k + dst) =
                            make_float2(f2tf32f(e2), f2tf32f(o2));
                    }
                }
            }
        }
    }
}

// ---------------------------------------------------------------------------
// Proj GEMM (plain epilogue)
// ---------------------------------------------------------------------------
__global__ __launch_bounds__(256) void gemm_proj_kernel(float* __restrict__ out) {
    const int bm = blockIdx.y * 128;
    const int bn = blockIdx.x * 128;
    float acc[4][4][4];
    gemm_mainloop(g_o, g_wprojc, DIM, DIM, bm, bn, acc);

    const int tid  = threadIdx.x;
    const int wid  = tid >> 5;
    const int lane = tid & 31;
    const int g    = lane >> 2;
    const int t    = lane & 3;
    const int wm   = (wid >> 2) * 64;
    const int wn   = (wid & 3) * 32;

#pragma unroll
    for (int mt = 0; mt < 4; mt++) {
#pragma unroll
        for (int nt = 0; nt < 4; nt++) {
            int r0 = bm + wm + mt * 16 + g;
            int cc = bn + wn + nt * 8 + 2 * t;
            *(float2*)(out + (size_t)r0 * DIM + cc)       = make_float2(acc[mt][nt][0], acc[mt][nt][1]);
            *(float2*)(out + (size_t)(r0 + 8) * DIM + cc) = make_float2(acc[mt][nt][2], acc[mt][nt][3]);
        }
    }
}

// ---------------------------------------------------------------------------
// Flash attention, tf32 mma, 2-stage cp.async KV pipeline, STATIC smem.
// KV tile = 32 rows (double-buffered: 35 KB).  256 thr / 8 warps, 128 q rows.
// ---------------------------------------------------------------------------
#define KS_S 68
#define VS_S 72
__global__ __launch_bounds__(256, 1) void attn_kernel() {
    __shared__ __align__(16) float Ks[2][32][KS_S];
    __shared__ __align__(16) float Vs[2][32][VS_S];

    const int bh   = blockIdx.y;
    const int q0   = blockIdx.x * 128;
    const int tid  = threadIdx.x;
    const int wid  = tid >> 5;
    const int lane = tid & 31;
    const int g    = lane >> 2;
    const int t    = lane & 3;

    const float* Kbase = g_k + (size_t)bh * TT * HD;
    const float* Vbase = g_v + (size_t)bh * TT * HD;

    auto load_kv = [&](int kv0, int bi) {
        // 32 rows x 16 float4 per matrix = 512 chunks each; 2+2 per thread
#pragma unroll
        for (int i = 0; i < 2; i++) {
            int idx = tid + i * 256;
            int row = idx >> 4, c4 = (idx & 15) << 2;
            cp16(s2u(&Ks[bi][row][c4]), Kbase + (size_t)(kv0 + row) * HD + c4);
            cp16(s2u(&Vs[bi][row][c4]), Vbase + (size_t)(kv0 + row) * HD + c4);
        }
    };

    // Q fragments: already tf32-rounded and pre-scaled
    const size_t qbase = ((size_t)bh * TT + q0 + wid * 16) * HD;
    uint32_t qa[8][4];
#pragma unroll
    for (int kt = 0; kt < 8; kt++) {
        qa[kt][0] = __float_as_uint(g_q[qbase + (size_t)g * HD + kt * 8 + t]);
        qa[kt][1] = __float_as_uint(g_q[qbase + (size_t)(g + 8) * HD + kt * 8 + t]);
        qa[kt][2] = __float_as_uint(g_q[qbase + (size_t)g * HD + kt * 8 + t + 4]);
        qa[kt][3] = __float_as_uint(g_q[qbase + (size_t)(g + 8) * HD + kt * 8 + t + 4]);
    }

    float O[8][4];
#pragma unroll
    for (int nt = 0; nt < 8; nt++)
#pragma unroll
        for (int r = 0; r < 4; r++) O[nt][r] = 0.f;
    float m0 = -1e30f, m1 = -1e30f, l0 = 0.f, l1 = 0.f;

    load_kv(0, 0);
    cp_commit();

    int bi = 0;
    for (int kv0 = 0; kv0 < TT; kv0 += 32, bi ^= 1) {
        cp_wait0();
        __syncthreads();
        if (kv0 + 32 < TT) load_kv(kv0 + 32, bi ^ 1);
        cp_commit();

        // S = Q @ K^T : warp computes [16 x 32]
        float s[4][4];
#pragma unroll
        for (int nt = 0; nt < 4; nt++)
#pragma unroll
            for (int r = 0; r < 4; r++) s[nt][r] = 0.f;
#pragma unroll
        for (int kt = 0; kt < 8; kt++) {
            uint32_t kb[4][2];
#pragma unroll
            for (int nt = 0; nt < 4; nt++) {
                kb[nt][0] = __float_as_uint(Ks[bi][nt * 8 + g][kt * 8 + t]);
                kb[nt][1] = __float_as_uint(Ks[bi][nt * 8 + g][kt * 8 + t + 4]);
            }
#pragma unroll
            for (int nt = 0; nt < 4; nt++)
                mma_tf32(s[nt], qa[kt], kb[nt]);
        }

        // online softmax (32-key cadence)
        float mx0 = -1e30f, mx1 = -1e30f;
#pragma unroll
        for (int nt = 0; nt < 4; nt++) {
            mx0 = fmaxf(mx0, fmaxf(s[nt][0], s[nt][1]));
            mx1 = fmaxf(mx1, fmaxf(s[nt][2], s[nt][3]));
        }
        mx0 = fmaxf(mx0, __shfl_xor_sync(0xffffffffu, mx0, 1));
        mx0 = fmaxf(mx0, __shfl_xor_sync(0xffffffffu, mx0, 2));
        mx1 = fmaxf(mx1, __shfl_xor_sync(0xffffffffu, mx1, 1));
        mx1 = fmaxf(mx1, __shfl_xor_sync(0xffffffffu, mx1, 2));
        float nm0 = fmaxf(m0, mx0), nm1 = fmaxf(m1, mx1);
        float c0 = __expf(m0 - nm0), c1 = __expf(m1 - nm1);
        m0 = nm0; m1 = nm1;
        l0 *= c0;  l1 *= c1;
#pragma unroll
        for (int nt = 0; nt < 8; nt++) {
            O[nt][0] *= c0; O[nt][1] *= c0;
            O[nt][2] *= c1; O[nt][3] *= c1;
        }
        uint32_t p[4][4];
#pragma unroll
        for (int nt = 0; nt < 4; nt++) {
            float e0 = __expf(s[nt][0] - m0);
            float e1 = __expf(s[nt][1] - m0);
            float e2 = __expf(s[nt][2] - m1);
            float e3 = __expf(s[nt][3] - m1);
            l0 += e0 + e1;  l1 += e2 + e3;
            p[nt][0] = f2tf32(e0); p[nt][1] = f2tf32(e1);
            p[nt][2] = f2tf32(e2); p[nt][3] = f2tf32(e3);
        }

        // O += P @ V.  P C-layout -> A-layout via shuffles.
#pragma unroll
        for (int kt = 0; kt < 4; kt++) {
            int base = lane & 28;
            int src0 = base + (t >> 1);
            int src1 = base + (t >> 1) + 2;
            uint32_t x00 = __shfl_sync(0xffffffffu, p[kt][0], src0);
            uint32_t x01 = __shfl_sync(0xffffffffu, p[kt][1], src0);
            uint32_t x02 = __shfl_sync(0xffffffffu, p[kt][2], src0);
            uint32_t x03 = __shfl_sync(0xffffffffu, p[kt][3], src0);
            uint32_t x10 = __shfl_sync(0xffffffffu, p[kt][0], src1);
            uint32_t x11 = __shfl_sync(0xffffffffu, p[kt][1], src1);
            uint32_t x12 = __shfl_sync(0xffffffffu, p[kt][2], src1);
            uint32_t x13 = __shfl_sync(0xffffffffu, p[kt][3], src1);
            uint32_t pa[4];
            pa[0] = (t & 1) ? x01 : x00;
            pa[1] = (t & 1) ? x03 : x02;
            pa[2] = (t & 1) ? x11 : x10;
            pa[3] = (t & 1) ? x13 : x12;
#pragma unroll
            for (int nt = 0; nt < 8; nt++) {
                uint32_t vb[2];
                vb[0] = __float_as_uint(Vs[bi][kt * 8 + t][nt * 8 + g]);
                vb[1] = __float_as_uint(Vs[bi][kt * 8 + t + 4][nt * 8 + g]);
                mma_tf32(O[nt], pa, vb);
            }
        }
    }

    // final normalize + tf32-round + write to g_o [b, t, h*d]
    l0 += __shfl_xor_sync(0xffffffffu, l0, 1);
    l0 += __shfl_xor_sync(0xffffffffu, l0, 2);
    l1 += __shfl_xor_sync(0xffffffffu, l1, 1);
    l1 += __shfl_xor_sync(0xffffffffu, l1, 2);
    float inv0 = 1.f / l0, inv1 = 1.f / l1;

    int b = bh >> 4, h = bh & 15;
    int r0 = q0 + wid * 16 + g;
#pragma unroll
    for (int nt = 0; nt < 8; nt++) {
        int cc = h * HD + nt * 8 + 2 * t;
        *(float2*)(g_o + ((size_t)(b * TT + r0)) * DIM + cc) =
            make_float2(f2tf32f(O[nt][0] * inv0), f2tf32f(O[nt][1] * inv0));
        *(float2*)(g_o + ((size_t)(b * TT + r0 + 8)) * DIM + cc) =
            make_float2(f2tf32f(O[nt][2] * inv1), f2tf32f(O[nt][3] * inv1));
    }
}

// ---------------------------------------------------------------------------
// Launch
// ---------------------------------------------------------------------------
extern "C" void kernel_launch(void* const* d_in, const int* in_sizes, int n_in,
                              void* d_out, int out_size) {
    (void)in_sizes; (void)n_in; (void)out_size;
    const float* x     = (const float*)d_in[0];
    const float* fcos  = (const float*)d_in[1];
    const float* fsin  = (const float*)d_in[2];
    const float* Wqkv  = (const float*)d_in[4];
    const float* Wproj = (const float*)d_in[5];
    float* out = (float*)d_out;

    float* xc;   cudaGetSymbolAddress((void**)&xc,   g_xc);
    float* wqc;  cudaGetSymbolAddress((void**)&wqc,  g_wqkvc);
    float* wpc;  cudaGetSymbolAddress((void**)&wpc,  g_wprojc);

    // tf32 pre-round passes
    {
        int n4 = MROWS * DIM / 4;
        tf32_cvt_kernel<<<n4 / 256, 256>>>((const float4*)x, (float4*)xc, n4);
    }
    {
        int n4 = DIM * 3 * DIM / 4;
        tf32_cvt_kernel<<<n4 / 256, 256>>>((const float4*)Wqkv, (float4*)wqc, n4);
    }
    {
        int n4 = DIM * DIM / 4;
        tf32_cvt_kernel<<<n4 / 256, 256>>>((const float4*)Wproj, (float4*)wpc, n4);
    }

    // QKV GEMM with fused RoPE+split epilogue
    {
        dim3 grid(3 * DIM / 128, MROWS / 128);
        gemm_qkv_kernel<<<grid, 256>>>(fcos, fsin);
    }
    // Flash attention (pipelined KV)
    {
        dim3 grid(TT / 128, BB * NH);
        attn_kernel<<<grid, 256>>>();
    }
    // Output projection
    {
        dim3 grid(DIM / 128, MROWS / 128);
        gemm_proj_kernel<<<grid, 256>>>(out);
    }
}